// round 3
// baseline (speedup 1.0000x reference)
#include <cuda_runtime.h>
#include <math.h>

// ---------------------------------------------------------------------------
// SimGNN on GB300: two independent GCN stacks -> attention pooling -> NTN -> MLP
// ---------------------------------------------------------------------------

#define MAXN 100000

// Scratch (device globals: allocation-free per harness rules)
__device__ __align__(16) float g_xw  [(size_t)MAXN * 128];
__device__ __align__(16) float g_agg0[(size_t)MAXN * 128];
__device__ __align__(16) float g_agg1[(size_t)MAXN * 128];
__device__ __align__(16) float g_dinv[MAXN];
__device__ __align__(16) int   g_deg [MAXN];
__device__ __align__(16) float g_colsum[64];
__device__ __align__(16) float g_gc[64];
__device__ __align__(16) float g_h[128];   // [0:64)=h_i, [64:128)=h_j

// ---------------------------------------------------------------------------
__global__ void zero_i32_kernel(int* __restrict__ p, int n) {
    int i = blockIdx.x * blockDim.x + threadIdx.x;
    if (i < n) p[i] = 0;
}

__global__ void zero_f32_kernel(float* __restrict__ p, int n) {
    int i = blockIdx.x * blockDim.x + threadIdx.x;
    if (i < n) p[i] = 0.f;
}

__global__ void deg_kernel(const int* __restrict__ dst, int* __restrict__ deg, int E) {
    int i = blockIdx.x * blockDim.x + threadIdx.x;
    if (i < E) atomicAdd(&deg[dst[i]], 1);
}

__global__ void dinv_kernel(const int* __restrict__ deg, float* __restrict__ dinv, int n) {
    int i = blockIdx.x * blockDim.x + threadIdx.x;
    if (i < n) dinv[i] = rsqrtf((float)(deg[i] + 1));  // +1 self loop
}

// ---------------------------------------------------------------------------
// GEMM: xw = relu_fused(in) @ W ; agg = xw * dinv^2 (self-loop init).
// Block tile: 32 rows x DOUT cols. Thread tile 4x4. W + x tile in smem.
template<int DIN, int DOUT, bool FUSE>
__global__ void gemm_kernel(const float* __restrict__ in, const float* __restrict__ W,
                            const float* __restrict__ bprev, const float* __restrict__ dinv,
                            float* __restrict__ xw, float* __restrict__ agg, int n)
{
    extern __shared__ float sh[];
    float* Ws = sh;                   // DIN*DOUT
    float* xs = sh + DIN * DOUT;      // 32*DIN
    const int tid  = threadIdx.y * blockDim.x + threadIdx.x;
    const int nthr = blockDim.x * blockDim.y;

    for (int i = tid; i < DIN * DOUT / 4; i += nthr)
        ((float4*)Ws)[i] = ((const float4*)W)[i];

    const int row0 = blockIdx.x * 32;
    for (int i = tid; i < 32 * DIN / 4; i += nthr) {
        int r = i / (DIN / 4), kk = i % (DIN / 4);
        int row = row0 + r;
        float4 v = make_float4(0.f, 0.f, 0.f, 0.f);
        if (row < n) {
            v = ((const float4*)(in + (size_t)row * DIN))[kk];
            if (FUSE) {
                float4 b = ((const float4*)bprev)[kk];
                v.x = fmaxf(v.x + b.x, 0.f);
                v.y = fmaxf(v.y + b.y, 0.f);
                v.z = fmaxf(v.z + b.z, 0.f);
                v.w = fmaxf(v.w + b.w, 0.f);
            }
        }
        ((float4*)(xs + r * DIN))[kk] = v;
    }
    __syncthreads();

    const int c0 = threadIdx.x * 4;
    const int r0 = threadIdx.y * 4;
    float acc[4][4] = {};
#pragma unroll 16
    for (int k = 0; k < DIN; k++) {
        float4 b = *(const float4*)(Ws + k * DOUT + c0);
#pragma unroll
        for (int i = 0; i < 4; i++) {
            float a = xs[(r0 + i) * DIN + k];
            acc[i][0] = fmaf(a, b.x, acc[i][0]);
            acc[i][1] = fmaf(a, b.y, acc[i][1]);
            acc[i][2] = fmaf(a, b.z, acc[i][2]);
            acc[i][3] = fmaf(a, b.w, acc[i][3]);
        }
    }
#pragma unroll
    for (int i = 0; i < 4; i++) {
        int row = row0 + r0 + i;
        if (row >= n) continue;
        float dv = dinv[row];
        float d2 = dv * dv;
        float4 v = make_float4(acc[i][0], acc[i][1], acc[i][2], acc[i][3]);
        *(float4*)(xw  + (size_t)row * DOUT + c0) = v;
        float4 w4 = make_float4(v.x * d2, v.y * d2, v.z * d2, v.w * d2);
        *(float4*)(agg + (size_t)row * DOUT + c0) = w4;
    }
}

// ---------------------------------------------------------------------------
// Edge aggregation: agg[dst] += xw[src] * dinv[src]*dinv[dst].
// One thread handles 4 cols (float4); DOUT/4 threads per edge. v4 red.global.
template<int DOUT>
__global__ void edge_kernel(const int* __restrict__ src, const int* __restrict__ dst,
                            const float* __restrict__ xw, const float* __restrict__ dinv,
                            float* __restrict__ agg, int E)
{
    constexpr int TPE = DOUT / 4;
    long long gid = (long long)blockIdx.x * blockDim.x + threadIdx.x;
    int e = (int)(gid / TPE);
    int l = (int)(gid % TPE);
    if (e >= E) return;
    int s = __ldg(&src[e]);
    int d = __ldg(&dst[e]);
    float norm = __ldg(&dinv[s]) * __ldg(&dinv[d]);
    float4 v = *(const float4*)(xw + (size_t)s * DOUT + 4 * l);
    v.x *= norm; v.y *= norm; v.z *= norm; v.w *= norm;
    float* p = agg + (size_t)d * DOUT + 4 * l;
    asm volatile("red.global.add.v4.f32 [%0], {%1,%2,%3,%4};"
                 :: "l"(p), "f"(v.x), "f"(v.y), "f"(v.z), "f"(v.w) : "memory");
}

// ---------------------------------------------------------------------------
// Column sums over final features (bias applied later): partial per block.
__global__ void colsum_kernel(const float* __restrict__ agg, float* __restrict__ colsum, int n)
{
    __shared__ float sm[256];
    int c  = threadIdx.x & 63;
    int rl = threadIdx.x >> 6;  // 0..3
    float acc = 0.f;
    for (int row = blockIdx.x * 4 + rl; row < n; row += gridDim.x * 4)
        acc += agg[(size_t)row * 64 + c];
    sm[threadIdx.x] = acc;
    __syncthreads();
    if (threadIdx.x < 64) {
        float s = sm[c] + sm[64 + c] + sm[128 + c] + sm[192 + c];
        atomicAdd(&colsum[c], s);
    }
}

__global__ void gc_kernel(const float* __restrict__ colsum, const float* __restrict__ b2,
                          const float* __restrict__ Wa, float* __restrict__ gc, float invN)
{
    __shared__ float mean[64];
    int t = threadIdx.x;
    mean[t] = colsum[t] * invN + b2[t];
    __syncthreads();
    float acc = 0.f;
#pragma unroll
    for (int d = 0; d < 64; d++) acc += mean[d] * Wa[d * 64 + t];
    gc[t] = tanhf(acc);
}

// h += sum_n (x_n + b2) * sigmoid((x_n+b2) . gc). Warp per row, block partials.
__global__ void attpool_kernel(const float* __restrict__ agg, const float* __restrict__ b2,
                               const float* __restrict__ gc, float* __restrict__ h, int n)
{
    __shared__ float gcs[64], b2s[64];
    __shared__ float red[8][64];
    int tid = threadIdx.x;
    if (tid < 64) { gcs[tid] = gc[tid]; b2s[tid] = b2[tid]; }
    __syncthreads();
    int lane = tid & 31, w = tid >> 5;
    float gx = gcs[2 * lane], gy = gcs[2 * lane + 1];
    float bx = b2s[2 * lane], by = b2s[2 * lane + 1];
    float ax = 0.f, ay = 0.f;
    for (int row = blockIdx.x * 8 + w; row < n; row += gridDim.x * 8) {
        float2 v = *(const float2*)(agg + (size_t)row * 64 + 2 * lane);
        v.x += bx; v.y += by;
        float d = v.x * gx + v.y * gy;
#pragma unroll
        for (int o = 16; o; o >>= 1) d += __shfl_xor_sync(0xFFFFFFFFu, d, o);
        float att = 1.f / (1.f + expf(-d));
        ax += v.x * att; ay += v.y * att;
    }
    red[w][2 * lane] = ax; red[w][2 * lane + 1] = ay;
    __syncthreads();
    if (w == 0) {
        float sx = 0.f, sy = 0.f;
#pragma unroll
        for (int i = 0; i < 8; i++) { sx += red[i][2 * lane]; sy += red[i][2 * lane + 1]; }
        atomicAdd(&h[2 * lane], sx);
        atomicAdd(&h[2 * lane + 1], sy);
    }
}

// ---------------------------------------------------------------------------
// NTN + MLP + score head. Single block, 1024 threads.
__global__ void final_kernel(const float* __restrict__ h,
                             const float* __restrict__ Wt, const float* __restrict__ Wm,
                             const float* __restrict__ nb,
                             const float* __restrict__ w0, const float* __restrict__ bb0,
                             const float* __restrict__ w1, const float* __restrict__ bb1,
                             const float* __restrict__ w2, const float* __restrict__ bb2,
                             const float* __restrict__ w3, const float* __restrict__ bb3,
                             const float* __restrict__ sw, const float* __restrict__ sb,
                             float* __restrict__ out)
{
    __shared__ float hi[64], hj[64];
    __shared__ float part[1024];
    __shared__ float z[16];
    int t = threadIdx.x;
    if (t < 64) hi[t] = h[t];
    else if (t < 128) hj[t - 64] = h[t];
    __syncthreads();

    int k = t >> 6, e = t & 63;
    const float* wt = Wt + (size_t)k * 4096 + e;   // Wt[k][d][e], stride 64 over d
    float acc = 0.f;
#pragma unroll
    for (int d = 0; d < 64; d++) acc += hi[d] * wt[d * 64];
    part[t] = acc * hj[e];
    __syncthreads();

    if (t < 16) {
        float s = 0.f;
        for (int e2 = 0; e2 < 64; e2++) s += part[t * 64 + e2];
        float lin = 0.f;
        const float* wm = Wm + t * 128;
        for (int m = 0; m < 64; m++) lin += wm[m] * hi[m] + wm[64 + m] * hj[m];
        z[t] = tanhf(s + lin + nb[t]);
    }
    __syncthreads();

    if (t == 0) {
        float a[32], b[32];
        for (int j = 0; j < 32; j++) { float s = bb0[j]; for (int i = 0; i < 16; i++) s += z[i] * w0[i * 32 + j]; a[j] = fmaxf(s, 0.f); }
        for (int j = 0; j < 16; j++) { float s = bb1[j]; for (int i = 0; i < 32; i++) s += a[i] * w1[i * 16 + j]; b[j] = fmaxf(s, 0.f); }
        for (int j = 0; j <  8; j++) { float s = bb2[j]; for (int i = 0; i < 16; i++) s += b[i] * w2[i * 8 + j];  a[j] = fmaxf(s, 0.f); }
        for (int j = 0; j <  4; j++) { float s = bb3[j]; for (int i = 0; i <  8; i++) s += a[i] * w3[i * 4 + j];  b[j] = fmaxf(s, 0.f); }
        float s = sb[0];
        for (int i = 0; i < 4; i++) s += b[i] * sw[i];
        out[0] = s;
    }
}

// ---------------------------------------------------------------------------
extern "C" void kernel_launch(void* const* d_in, const int* in_sizes, int n_in,
                              void* d_out, int out_size)
{
    const float* x_i = (const float*)d_in[0];
    const int*   ei  = (const int*)d_in[1];     // int32 (JAX x64 disabled)
    const float* x_j = (const float*)d_in[2];
    const int*   ej  = (const int*)d_in[3];
    const float* w0 = (const float*)d_in[4];
    const float* b0 = (const float*)d_in[5];
    const float* w1 = (const float*)d_in[6];
    const float* b1 = (const float*)d_in[7];
    const float* w2 = (const float*)d_in[8];
    const float* b2 = (const float*)d_in[9];
    const float* att_w  = (const float*)d_in[10];
    const float* ntn_wt = (const float*)d_in[11];
    const float* ntn_wm = (const float*)d_in[12];
    const float* ntn_b  = (const float*)d_in[13];
    const float* mw0 = (const float*)d_in[14];
    const float* mb0 = (const float*)d_in[15];
    const float* mw1 = (const float*)d_in[16];
    const float* mb1 = (const float*)d_in[17];
    const float* mw2 = (const float*)d_in[18];
    const float* mb2 = (const float*)d_in[19];
    const float* mw3 = (const float*)d_in[20];
    const float* mb3 = (const float*)d_in[21];
    const float* sw  = (const float*)d_in[22];
    const float* sb  = (const float*)d_in[23];
    float* out = (float*)d_out;

    const int N = in_sizes[0] / 64;
    const int E = in_sizes[1] / 2;

    float *xwp, *agg0p, *agg1p, *dinvp, *colsump, *gcp, *hp;
    int* degp;
    cudaGetSymbolAddress((void**)&xwp,     g_xw);
    cudaGetSymbolAddress((void**)&agg0p,   g_agg0);
    cudaGetSymbolAddress((void**)&agg1p,   g_agg1);
    cudaGetSymbolAddress((void**)&dinvp,   g_dinv);
    cudaGetSymbolAddress((void**)&degp,    g_deg);
    cudaGetSymbolAddress((void**)&colsump, g_colsum);
    cudaGetSymbolAddress((void**)&gcp,     g_gc);
    cudaGetSymbolAddress((void**)&hp,      g_h);

    const int smem0 = (64  * 128 + 32 * 64 ) * 4;   // 40960
    const int smem1 = (128 * 128 + 32 * 128) * 4;   // 81920
    const int smem2 = (128 * 64  + 32 * 128) * 4;   // 49152
    cudaFuncSetAttribute(gemm_kernel<64, 128, false>, cudaFuncAttributeMaxDynamicSharedMemorySize, smem0);
    cudaFuncSetAttribute(gemm_kernel<128, 128, true>, cudaFuncAttributeMaxDynamicSharedMemorySize, smem1);
    cudaFuncSetAttribute(gemm_kernel<128, 64,  true>, cudaFuncAttributeMaxDynamicSharedMemorySize, smem2);

    const int gemm_blocks = (N + 31) / 32;
    const long long eth128 = (long long)E * 32;
    const long long eth64  = (long long)E * 16;
    const int eb128 = (int)((eth128 + 255) / 256);
    const int eb64  = (int)((eth64  + 255) / 256);

    // Zero h accumulator (graph-capturable kernel, NOT cudaMemsetAsync on symbol)
    zero_f32_kernel<<<1, 128>>>(hp, 128);

    for (int g = 0; g < 2; g++) {
        const float* x    = (g == 0) ? x_i : x_j;
        const int*   eidx = (g == 0) ? ei  : ej;
        const int*   src  = eidx;
        const int*   dst  = eidx + E;
        float* hout = hp + g * 64;

        zero_i32_kernel<<<(N + 255) / 256, 256>>>(degp, N);
        deg_kernel<<<(E + 255) / 256, 256>>>(dst, degp, E);
        dinv_kernel<<<(N + 255) / 256, 256>>>(degp, dinvp, N);

        // Layer 0: 64 -> 128
        gemm_kernel<64, 128, false><<<gemm_blocks, dim3(32, 8), smem0>>>(x, w0, nullptr, dinvp, xwp, agg0p, N);
        edge_kernel<128><<<eb128, 256>>>(src, dst, xwp, dinvp, agg0p, E);
        // Layer 1: 128 -> 128 (bias0 + relu fused into input read)
        gemm_kernel<128, 128, true><<<gemm_blocks, dim3(32, 8), smem1>>>(agg0p, w1, b0, dinvp, xwp, agg1p, N);
        edge_kernel<128><<<eb128, 256>>>(src, dst, xwp, dinvp, agg1p, E);
        // Layer 2: 128 -> 64 (bias1 + relu fused)
        gemm_kernel<128, 64, true><<<gemm_blocks, dim3(16, 8), smem2>>>(agg1p, w2, b1, dinvp, xwp, agg0p, N);
        edge_kernel<64><<<eb64, 256>>>(src, dst, xwp, dinvp, agg0p, E);

        // Attention pooling (bias2 applied on the fly; no relu on last layer)
        zero_f32_kernel<<<1, 64>>>(colsump, 64);
        colsum_kernel<<<512, 256>>>(agg0p, colsump, N);
        gc_kernel<<<1, 64>>>(colsump, b2, att_w, gcp, 1.0f / (float)N);
        attpool_kernel<<<592, 256>>>(agg0p, b2, gcp, hout, N);
    }

    final_kernel<<<1, 1024>>>(hp, ntn_wt, ntn_wm, ntn_b,
                              mw0, mb0, mw1, mb1, mw2, mb2, mw3, mb3,
                              sw, sb, out);
}

// round 4
// speedup vs baseline: 1.4411x; 1.4411x over previous
#include <cuda_runtime.h>
#include <math.h>

// ---------------------------------------------------------------------------
// SimGNN on GB300: two GCN stacks (CSR gather aggregation) -> attention pooling
// -> NTN -> MLP
// ---------------------------------------------------------------------------

#define MAXN 100000
#define MAXE 1300000

__device__ __align__(16) float g_xw  [(size_t)MAXN * 128];
__device__ __align__(16) float g_agg0[(size_t)MAXN * 128];
__device__ __align__(16) float g_agg1[(size_t)MAXN * 128];
__device__ __align__(16) float g_dinv[MAXN];
__device__ __align__(16) int   g_deg [MAXN];
__device__ __align__(16) int   g_off [MAXN + 1];
__device__ __align__(16) int   g_cur [MAXN];
__device__ __align__(16) int   g_part[256];
__device__ __align__(16) int2  g_csr [MAXE];
__device__ __align__(16) float g_colsum[64];
__device__ __align__(16) float g_gc[64];
__device__ __align__(16) float g_h[128];   // [0:64)=h_i, [64:128)=h_j

// ---------------------------------------------------------------------------
__global__ void zero_i32_kernel(int* __restrict__ p, int n) {
    int i = blockIdx.x * blockDim.x + threadIdx.x;
    if (i < n) p[i] = 0;
}

__global__ void zero_f32_kernel(float* __restrict__ p, int n) {
    int i = blockIdx.x * blockDim.x + threadIdx.x;
    if (i < n) p[i] = 0.f;
}

__global__ void deg_kernel(const int* __restrict__ dst, int* __restrict__ deg, int E) {
    int i = blockIdx.x * blockDim.x + threadIdx.x;
    if (i < E) atomicAdd(&deg[dst[i]], 1);
}

__global__ void dinv_kernel(const int* __restrict__ deg, float* __restrict__ dinv, int n) {
    int i = blockIdx.x * blockDim.x + threadIdx.x;
    if (i < n) dinv[i] = rsqrtf((float)(deg[i] + 1));  // +1 self loop
}

// --------------------------- CSR build: scan ------------------------------
// Pass 1: per-1024-block exclusive scan; block totals to partials.
__global__ void scan1_kernel(const int* __restrict__ deg, int* __restrict__ off,
                             int* __restrict__ partials, int n)
{
    __shared__ int wsum[32];
    int gid  = blockIdx.x * 1024 + threadIdx.x;
    int lane = threadIdx.x & 31, wid = threadIdx.x >> 5;
    int v = (gid < n) ? deg[gid] : 0;
    int x = v;
#pragma unroll
    for (int o = 1; o < 32; o <<= 1) {
        int y = __shfl_up_sync(0xFFFFFFFFu, x, o);
        if (lane >= o) x += y;
    }
    if (lane == 31) wsum[wid] = x;
    __syncthreads();
    if (wid == 0) {
        int s = wsum[lane];
#pragma unroll
        for (int o = 1; o < 32; o <<= 1) {
            int y = __shfl_up_sync(0xFFFFFFFFu, s, o);
            if (lane >= o) s += y;
        }
        wsum[lane] = s;
    }
    __syncthreads();
    int excl = (wid > 0 ? wsum[wid - 1] : 0) + x - v;
    if (gid < n) off[gid] = excl;
    if (threadIdx.x == 1023) partials[blockIdx.x] = wsum[31];
}

// Pass 2: serial exclusive scan of block partials (nb <= 128).
__global__ void scan2_kernel(int* __restrict__ partials, int nb)
{
    if (threadIdx.x == 0) {
        int run = 0;
        for (int i = 0; i < nb; i++) { int t = partials[i]; partials[i] = run; run += t; }
    }
}

// Pass 3: add block offsets; init cursor; write off[n].
__global__ void scan3_kernel(int* __restrict__ off, const int* __restrict__ partials,
                             int* __restrict__ cur, const int* __restrict__ deg, int n)
{
    int gid = blockIdx.x * blockDim.x + threadIdx.x;
    if (gid < n) {
        int o = off[gid] + partials[gid >> 10];
        off[gid] = o;
        cur[gid] = o;
        if (gid == n - 1) off[n] = o + deg[gid];
    }
}

// Scatter edges into CSR: csr[pos] = (src, dinv[src]) for each dst bucket.
__global__ void scatter_kernel(const int* __restrict__ src, const int* __restrict__ dst,
                               const float* __restrict__ dinv, int* __restrict__ cur,
                               int2* __restrict__ csr, int E)
{
    int e = blockIdx.x * blockDim.x + threadIdx.x;
    if (e >= E) return;
    int s = src[e], d = dst[e];
    int pos = atomicAdd(&cur[d], 1);
    csr[pos] = make_int2(s, __float_as_int(__ldg(&dinv[s])));
}

// ---------------------------------------------------------------------------
// GEMM: xw = relu_fused(in) @ W. Block tile: 32 rows x DOUT. Thread tile 4x4.
template<int DIN, int DOUT, bool FUSE>
__global__ void gemm_kernel(const float* __restrict__ in, const float* __restrict__ W,
                            const float* __restrict__ bprev, float* __restrict__ xw, int n)
{
    extern __shared__ float sh[];
    float* Ws = sh;                   // DIN*DOUT
    float* xs = sh + DIN * DOUT;      // 32*DIN
    const int tid  = threadIdx.y * blockDim.x + threadIdx.x;
    const int nthr = blockDim.x * blockDim.y;

    for (int i = tid; i < DIN * DOUT / 4; i += nthr)
        ((float4*)Ws)[i] = ((const float4*)W)[i];

    const int row0 = blockIdx.x * 32;
    for (int i = tid; i < 32 * DIN / 4; i += nthr) {
        int r = i / (DIN / 4), kk = i % (DIN / 4);
        int row = row0 + r;
        float4 v = make_float4(0.f, 0.f, 0.f, 0.f);
        if (row < n) {
            v = ((const float4*)(in + (size_t)row * DIN))[kk];
            if (FUSE) {
                float4 b = ((const float4*)bprev)[kk];
                v.x = fmaxf(v.x + b.x, 0.f);
                v.y = fmaxf(v.y + b.y, 0.f);
                v.z = fmaxf(v.z + b.z, 0.f);
                v.w = fmaxf(v.w + b.w, 0.f);
            }
        }
        ((float4*)(xs + r * DIN))[kk] = v;
    }
    __syncthreads();

    const int c0 = threadIdx.x * 4;
    const int r0 = threadIdx.y * 4;
    float acc[4][4] = {};
#pragma unroll 16
    for (int k = 0; k < DIN; k++) {
        float4 b = *(const float4*)(Ws + k * DOUT + c0);
#pragma unroll
        for (int i = 0; i < 4; i++) {
            float a = xs[(r0 + i) * DIN + k];
            acc[i][0] = fmaf(a, b.x, acc[i][0]);
            acc[i][1] = fmaf(a, b.y, acc[i][1]);
            acc[i][2] = fmaf(a, b.z, acc[i][2]);
            acc[i][3] = fmaf(a, b.w, acc[i][3]);
        }
    }
#pragma unroll
    for (int i = 0; i < 4; i++) {
        int row = row0 + r0 + i;
        if (row >= n) continue;
        *(float4*)(xw + (size_t)row * DOUT + c0) =
            make_float4(acc[i][0], acc[i][1], acc[i][2], acc[i][3]);
    }
}

// ---------------------------------------------------------------------------
// CSR aggregation: agg[d] = xw[d]*dinv[d]^2 + sum_in-edges dinv[s]*dinv[d]*xw[s].
// One warp per dst node; lane covers DOUT/32 columns. Two-edge unroll for MLP.
template<int DOUT>
__global__ void agg_csr_kernel(const int* __restrict__ off, const int2* __restrict__ csr,
                               const float* __restrict__ xw, const float* __restrict__ dinv,
                               float* __restrict__ agg, int n)
{
    constexpr int VEC = DOUT / 32;   // 4 or 2
    int node = blockIdx.x * 8 + (threadIdx.x >> 5);
    if (node >= n) return;
    int lane = threadIdx.x & 31;

    float dv = __ldg(&dinv[node]);
    const float* xr = xw + (size_t)node * DOUT + lane * VEC;
    float acc[VEC], acc2[VEC];
    if (VEC == 4) {
        float4 v = *(const float4*)xr;
        acc[0] = v.x * dv * dv; acc[1] = v.y * dv * dv;
        acc[2] = v.z * dv * dv; acc[3] = v.w * dv * dv;
        acc2[0] = acc2[1] = acc2[2] = acc2[3] = 0.f;
    } else {
        float2 v = *(const float2*)xr;
        acc[0] = v.x * dv * dv; acc[1] = v.y * dv * dv;
        acc2[0] = acc2[1] = 0.f;
    }

    int p = __ldg(&off[node]);
    int pend = __ldg(&off[node + 1]);
    for (; p + 2 <= pend; p += 2) {
        int2 e0 = __ldg(&csr[p]);
        int2 e1 = __ldg(&csr[p + 1]);
        float n0 = __int_as_float(e0.y) * dv;
        float n1 = __int_as_float(e1.y) * dv;
        const float* s0 = xw + (size_t)e0.x * DOUT + lane * VEC;
        const float* s1 = xw + (size_t)e1.x * DOUT + lane * VEC;
        if (VEC == 4) {
            float4 v0 = *(const float4*)s0;
            float4 v1 = *(const float4*)s1;
            acc[0] = fmaf(n0, v0.x, acc[0]); acc[1] = fmaf(n0, v0.y, acc[1]);
            acc[2] = fmaf(n0, v0.z, acc[2]); acc[3] = fmaf(n0, v0.w, acc[3]);
            acc2[0] = fmaf(n1, v1.x, acc2[0]); acc2[1] = fmaf(n1, v1.y, acc2[1]);
            acc2[2] = fmaf(n1, v1.z, acc2[2]); acc2[3] = fmaf(n1, v1.w, acc2[3]);
        } else {
            float2 v0 = *(const float2*)s0;
            float2 v1 = *(const float2*)s1;
            acc[0] = fmaf(n0, v0.x, acc[0]); acc[1] = fmaf(n0, v0.y, acc[1]);
            acc2[0] = fmaf(n1, v1.x, acc2[0]); acc2[1] = fmaf(n1, v1.y, acc2[1]);
        }
    }
    if (p < pend) {
        int2 e0 = __ldg(&csr[p]);
        float n0 = __int_as_float(e0.y) * dv;
        const float* s0 = xw + (size_t)e0.x * DOUT + lane * VEC;
        if (VEC == 4) {
            float4 v0 = *(const float4*)s0;
            acc[0] = fmaf(n0, v0.x, acc[0]); acc[1] = fmaf(n0, v0.y, acc[1]);
            acc[2] = fmaf(n0, v0.z, acc[2]); acc[3] = fmaf(n0, v0.w, acc[3]);
        } else {
            float2 v0 = *(const float2*)s0;
            acc[0] = fmaf(n0, v0.x, acc[0]); acc[1] = fmaf(n0, v0.y, acc[1]);
        }
    }

    float* o = agg + (size_t)node * DOUT + lane * VEC;
    if (VEC == 4)
        *(float4*)o = make_float4(acc[0] + acc2[0], acc[1] + acc2[1],
                                  acc[2] + acc2[2], acc[3] + acc2[3]);
    else
        *(float2*)o = make_float2(acc[0] + acc2[0], acc[1] + acc2[1]);
}

// ---------------------------------------------------------------------------
__global__ void colsum_kernel(const float* __restrict__ agg, float* __restrict__ colsum, int n)
{
    __shared__ float sm[256];
    int c  = threadIdx.x & 63;
    int rl = threadIdx.x >> 6;
    float acc = 0.f;
    for (int row = blockIdx.x * 4 + rl; row < n; row += gridDim.x * 4)
        acc += agg[(size_t)row * 64 + c];
    sm[threadIdx.x] = acc;
    __syncthreads();
    if (threadIdx.x < 64) {
        float s = sm[c] + sm[64 + c] + sm[128 + c] + sm[192 + c];
        atomicAdd(&colsum[c], s);
    }
}

__global__ void gc_kernel(const float* __restrict__ colsum, const float* __restrict__ b2,
                          const float* __restrict__ Wa, float* __restrict__ gc, float invN)
{
    __shared__ float mean[64];
    int t = threadIdx.x;
    mean[t] = colsum[t] * invN + b2[t];
    __syncthreads();
    float acc = 0.f;
#pragma unroll
    for (int d = 0; d < 64; d++) acc += mean[d] * Wa[d * 64 + t];
    gc[t] = tanhf(acc);
}

__global__ void attpool_kernel(const float* __restrict__ agg, const float* __restrict__ b2,
                               const float* __restrict__ gc, float* __restrict__ h, int n)
{
    __shared__ float gcs[64], b2s[64];
    __shared__ float red[8][64];
    int tid = threadIdx.x;
    if (tid < 64) { gcs[tid] = gc[tid]; b2s[tid] = b2[tid]; }
    __syncthreads();
    int lane = tid & 31, w = tid >> 5;
    float gx = gcs[2 * lane], gy = gcs[2 * lane + 1];
    float bx = b2s[2 * lane], by = b2s[2 * lane + 1];
    float ax = 0.f, ay = 0.f;
    for (int row = blockIdx.x * 8 + w; row < n; row += gridDim.x * 8) {
        float2 v = *(const float2*)(agg + (size_t)row * 64 + 2 * lane);
        v.x += bx; v.y += by;
        float d = v.x * gx + v.y * gy;
#pragma unroll
        for (int o = 16; o; o >>= 1) d += __shfl_xor_sync(0xFFFFFFFFu, d, o);
        float att = 1.f / (1.f + expf(-d));
        ax += v.x * att; ay += v.y * att;
    }
    red[w][2 * lane] = ax; red[w][2 * lane + 1] = ay;
    __syncthreads();
    if (w == 0) {
        float sx = 0.f, sy = 0.f;
#pragma unroll
        for (int i = 0; i < 8; i++) { sx += red[i][2 * lane]; sy += red[i][2 * lane + 1]; }
        atomicAdd(&h[2 * lane], sx);
        atomicAdd(&h[2 * lane + 1], sy);
    }
}

// ---------------------------------------------------------------------------
__global__ void final_kernel(const float* __restrict__ h,
                             const float* __restrict__ Wt, const float* __restrict__ Wm,
                             const float* __restrict__ nb,
                             const float* __restrict__ w0, const float* __restrict__ bb0,
                             const float* __restrict__ w1, const float* __restrict__ bb1,
                             const float* __restrict__ w2, const float* __restrict__ bb2,
                             const float* __restrict__ w3, const float* __restrict__ bb3,
                             const float* __restrict__ sw, const float* __restrict__ sb,
                             float* __restrict__ out)
{
    __shared__ float hi[64], hj[64];
    __shared__ float part[1024];
    __shared__ float z[16];
    int t = threadIdx.x;
    if (t < 64) hi[t] = h[t];
    else if (t < 128) hj[t - 64] = h[t];
    __syncthreads();

    int k = t >> 6, e = t & 63;
    const float* wt = Wt + (size_t)k * 4096 + e;
    float acc = 0.f;
#pragma unroll
    for (int d = 0; d < 64; d++) acc += hi[d] * wt[d * 64];
    part[t] = acc * hj[e];
    __syncthreads();

    if (t < 16) {
        float s = 0.f;
        for (int e2 = 0; e2 < 64; e2++) s += part[t * 64 + e2];
        float lin = 0.f;
        const float* wm = Wm + t * 128;
        for (int m = 0; m < 64; m++) lin += wm[m] * hi[m] + wm[64 + m] * hj[m];
        z[t] = tanhf(s + lin + nb[t]);
    }
    __syncthreads();

    if (t == 0) {
        float a[32], b[32];
        for (int j = 0; j < 32; j++) { float s = bb0[j]; for (int i = 0; i < 16; i++) s += z[i] * w0[i * 32 + j]; a[j] = fmaxf(s, 0.f); }
        for (int j = 0; j < 16; j++) { float s = bb1[j]; for (int i = 0; i < 32; i++) s += a[i] * w1[i * 16 + j]; b[j] = fmaxf(s, 0.f); }
        for (int j = 0; j <  8; j++) { float s = bb2[j]; for (int i = 0; i < 16; i++) s += b[i] * w2[i * 8 + j];  a[j] = fmaxf(s, 0.f); }
        for (int j = 0; j <  4; j++) { float s = bb3[j]; for (int i = 0; i <  8; i++) s += a[i] * w3[i * 4 + j];  b[j] = fmaxf(s, 0.f); }
        float s = sb[0];
        for (int i = 0; i < 4; i++) s += b[i] * sw[i];
        out[0] = s;
    }
}

// ---------------------------------------------------------------------------
extern "C" void kernel_launch(void* const* d_in, const int* in_sizes, int n_in,
                              void* d_out, int out_size)
{
    const float* x_i = (const float*)d_in[0];
    const int*   ei  = (const int*)d_in[1];     // int32 (JAX x64 disabled)
    const float* x_j = (const float*)d_in[2];
    const int*   ej  = (const int*)d_in[3];
    const float* w0 = (const float*)d_in[4];
    const float* b0 = (const float*)d_in[5];
    const float* w1 = (const float*)d_in[6];
    const float* b1 = (const float*)d_in[7];
    const float* w2 = (const float*)d_in[8];
    const float* b2 = (const float*)d_in[9];
    const float* att_w  = (const float*)d_in[10];
    const float* ntn_wt = (const float*)d_in[11];
    const float* ntn_wm = (const float*)d_in[12];
    const float* ntn_b  = (const float*)d_in[13];
    const float* mw0 = (const float*)d_in[14];
    const float* mb0 = (const float*)d_in[15];
    const float* mw1 = (const float*)d_in[16];
    const float* mb1 = (const float*)d_in[17];
    const float* mw2 = (const float*)d_in[18];
    const float* mb2 = (const float*)d_in[19];
    const float* mw3 = (const float*)d_in[20];
    const float* mb3 = (const float*)d_in[21];
    const float* sw  = (const float*)d_in[22];
    const float* sb  = (const float*)d_in[23];
    float* out = (float*)d_out;

    const int N = in_sizes[0] / 64;
    const int E = in_sizes[1] / 2;

    float *xwp, *agg0p, *agg1p, *dinvp, *colsump, *gcp, *hp;
    int *degp, *offp, *curp, *partp;
    int2* csrp;
    cudaGetSymbolAddress((void**)&xwp,     g_xw);
    cudaGetSymbolAddress((void**)&agg0p,   g_agg0);
    cudaGetSymbolAddress((void**)&agg1p,   g_agg1);
    cudaGetSymbolAddress((void**)&dinvp,   g_dinv);
    cudaGetSymbolAddress((void**)&degp,    g_deg);
    cudaGetSymbolAddress((void**)&offp,    g_off);
    cudaGetSymbolAddress((void**)&curp,    g_cur);
    cudaGetSymbolAddress((void**)&partp,   g_part);
    cudaGetSymbolAddress((void**)&csrp,    g_csr);
    cudaGetSymbolAddress((void**)&colsump, g_colsum);
    cudaGetSymbolAddress((void**)&gcp,     g_gc);
    cudaGetSymbolAddress((void**)&hp,      g_h);

    const int smem0 = (64  * 128 + 32 * 64 ) * 4;
    const int smem1 = (128 * 128 + 32 * 128) * 4;
    const int smem2 = (128 * 64  + 32 * 128) * 4;
    cudaFuncSetAttribute(gemm_kernel<64, 128, false>, cudaFuncAttributeMaxDynamicSharedMemorySize, smem0);
    cudaFuncSetAttribute(gemm_kernel<128, 128, true>, cudaFuncAttributeMaxDynamicSharedMemorySize, smem1);
    cudaFuncSetAttribute(gemm_kernel<128, 64,  true>, cudaFuncAttributeMaxDynamicSharedMemorySize, smem2);

    const int gemm_blocks = (N + 31) / 32;
    const int agg_blocks  = (N + 7) / 8;
    const int scan_blocks = (N + 1023) / 1024;

    zero_f32_kernel<<<1, 128>>>(hp, 128);

    for (int g = 0; g < 2; g++) {
        const float* x    = (g == 0) ? x_i : x_j;
        const int*   eidx = (g == 0) ? ei  : ej;
        const int*   src  = eidx;
        const int*   dst  = eidx + E;
        float* hout = hp + g * 64;

        // Degree + norm + CSR build (once per graph, reused for 3 layers)
        zero_i32_kernel<<<(N + 255) / 256, 256>>>(degp, N);
        deg_kernel<<<(E + 255) / 256, 256>>>(dst, degp, E);
        dinv_kernel<<<(N + 255) / 256, 256>>>(degp, dinvp, N);
        scan1_kernel<<<scan_blocks, 1024>>>(degp, offp, partp, N);
        scan2_kernel<<<1, 32>>>(partp, scan_blocks);
        scan3_kernel<<<(N + 255) / 256, 256>>>(offp, partp, curp, degp, N);
        scatter_kernel<<<(E + 255) / 256, 256>>>(src, dst, dinvp, curp, csrp, E);

        // Layer 0: 64 -> 128
        gemm_kernel<64, 128, false><<<gemm_blocks, dim3(32, 8), smem0>>>(x, w0, nullptr, xwp, N);
        agg_csr_kernel<128><<<agg_blocks, 256>>>(offp, csrp, xwp, dinvp, agg0p, N);
        // Layer 1: 128 -> 128 (bias0 + relu fused)
        gemm_kernel<128, 128, true><<<gemm_blocks, dim3(32, 8), smem1>>>(agg0p, w1, b0, xwp, N);
        agg_csr_kernel<128><<<agg_blocks, 256>>>(offp, csrp, xwp, dinvp, agg1p, N);
        // Layer 2: 128 -> 64 (bias1 + relu fused)
        gemm_kernel<128, 64, true><<<gemm_blocks, dim3(16, 8), smem2>>>(agg1p, w2, b1, xwp, N);
        agg_csr_kernel<64><<<agg_blocks, 256>>>(offp, csrp, xwp, dinvp, agg0p, N);

        // Attention pooling (bias2 applied on the fly)
        zero_f32_kernel<<<1, 64>>>(colsump, 64);
        colsum_kernel<<<512, 256>>>(agg0p, colsump, N);
        gc_kernel<<<1, 64>>>(colsump, b2, att_w, gcp, 1.0f / (float)N);
        attpool_kernel<<<592, 256>>>(agg0p, b2, gcp, hout, N);
    }

    final_kernel<<<1, 1024>>>(hp, ntn_wt, ntn_wm, ntn_b,
                              mw0, mb0, mw1, mb1, mw2, mb2, mw3, mb3,
                              sw, sb, out);
}